// round 14
// baseline (speedup 1.0000x reference)
#include <cuda_runtime.h>
#include <cstdint>

// CRF forward (linear-chain log-partition), B=64, T=2048, K=256.
// 1 cluster (2 CTAs) per batch row, 512 threads/CTA. Row-split: CTA r owns the
// 128 next-states j in [r*128, r*128+128), E[j,i]=exp(trans[j,i]-Mj) register-
// resident (64 fp32/thread over a 64-wide i-chunk; 4 threads per j).
// Exp-domain scores: P = exp(s - C). Tail (128 threads) computes
// P' = yexp * v * rv  (no transcendentals on the serial path), publishes its
// half of P via st.async: packed b64, locally into mbarL (fast) and to the
// peer into mbarR (DSMEM). Warps over local i-chunks wait only mbarL, so the
// 215-cyc peer delivery overlaps their FMA. One __syncthreads per step.
// Shift bookkeeping (C, rv=1/v*) by thread JSTAR off the critical path.
// Masked suffix skipped entirely (mask is a prefix: len = sum mask).

#define KSZ 256
#define TSZ 2048
#define SOSI 2
#define JSTAR 16

__device__ __forceinline__ float ex2f(float x) {
    float r; asm("ex2.approx.ftz.f32 %0, %1;" : "=f"(r) : "f"(x)); return r;
}
__device__ __forceinline__ float lg2f_(float x) {
    float r; asm("lg2.approx.ftz.f32 %0, %1;" : "=f"(r) : "f"(x)); return r;
}
__device__ __forceinline__ float rcpf_(float x) {
    float r; asm("rcp.approx.ftz.f32 %0, %1;" : "=f"(r) : "f"(x)); return r;
}
__device__ __forceinline__ void unpack2(unsigned long long v, float& lo, float& hi) {
    asm("mov.b64 {%0, %1}, %2;" : "=f"(lo), "=f"(hi) : "l"(v));
}
__device__ __forceinline__ unsigned long long pack2(float lo, float hi) {
    unsigned long long r; asm("mov.b64 %0, {%1, %2};" : "=l"(r) : "f"(lo), "f"(hi)); return r;
}
__device__ __forceinline__ void fma2(unsigned long long& d, unsigned long long a, unsigned long long b) {
    asm("fma.rn.f32x2 %0, %1, %2, %0;" : "+l"(d) : "l"(a), "l"(b));
}
__device__ __forceinline__ uint32_t smem_u32(const void* p) {
    uint32_t a;
    asm("{ .reg .u64 t; cvta.to.shared.u64 t, %1; cvt.u32.u64 %0, t; }" : "=r"(a) : "l"(p));
    return a;
}
__device__ __forceinline__ uint32_t mapa_u32(uint32_t a, uint32_t rk) {
    uint32_t r; asm("mapa.shared::cluster.u32 %0, %1, %2;" : "=r"(r) : "r"(a), "r"(rk)); return r;
}
__device__ __forceinline__ void st_cl(uint32_t a, float v) {
    asm volatile("st.shared::cluster.f32 [%0], %1;" :: "r"(a), "f"(v));
}
__device__ __forceinline__ void st_async_b64(uint32_t dst_addr, unsigned long long v, uint32_t dst_bar) {
    asm volatile("st.async.shared::cluster.mbarrier::complete_tx::bytes.b64 [%0], %1, [%2];"
                 :: "r"(dst_addr), "l"(v), "r"(dst_bar) : "memory");
}
__device__ __forceinline__ void st_async_b32(uint32_t dst_addr, float v, uint32_t dst_bar) {
    asm volatile("st.async.shared::cluster.mbarrier::complete_tx::bytes.b32 [%0], %1, [%2];"
                 :: "r"(dst_addr), "r"(__float_as_uint(v)), "r"(dst_bar) : "memory");
}
__device__ __forceinline__ void mbar_init(uint32_t bar, uint32_t cnt) {
    asm volatile("mbarrier.init.shared.b64 [%0], %1;" :: "r"(bar), "r"(cnt) : "memory");
}
__device__ __forceinline__ void mbar_expect_tx(uint32_t bar, uint32_t bytes) {
    asm volatile("mbarrier.arrive.expect_tx.shared.b64 _, [%0], %1;" :: "r"(bar), "r"(bytes) : "memory");
}
__device__ __forceinline__ void mbar_wait_parity(uint32_t bar, uint32_t par) {
    asm volatile(
        "{\n\t.reg .pred P;\n\t"
        "WL_%=:\n\t"
        "mbarrier.try_wait.parity.acquire.cta.shared::cta.b64 P, [%0], %1, 0x989680;\n\t"
        "@P bra.uni WD_%=;\n\t"
        "bra.uni WL_%=;\n\t"
        "WD_%=:\n\t}"
        :: "r"(bar), "r"(par) : "memory");
}
__device__ __forceinline__ void cluster_barrier() {
    asm volatile("barrier.cluster.arrive.aligned;" ::: "memory");
    asm volatile("barrier.cluster.wait.aligned;"   ::: "memory");
}

__global__ void __cluster_dims__(2, 1, 1) __launch_bounds__(512, 1)
crf_fwd_kernel(const float* __restrict__ y,
               const float* __restrict__ mask,
               const float* __restrict__ trans,
               float* __restrict__ out)
{
    constexpr float INV_LN2 = 1.4426950408889634f;
    constexpr float LN2F    = 0.6931471805599453f;

    __shared__ __align__(16) float p_s[2][KSZ];     // full P vector, double-buffered
    __shared__ float partial_s[2][4][128];          // per-chunk partials, double-buffered
    __shared__ float Mrow_s[128];
    __shared__ float rv_s[2];                       // lagged 1/v*
    __shared__ float c_s;                           // final shift (rank 0)
    __shared__ float sfin_s[128];                   // final P, own half
    __shared__ float fin_s;                         // peer's half-sum
    __shared__ float lred_s[16];
    __shared__ int   len_s;
    __shared__ __align__(8) unsigned long long mbarL[2]; // own-half p delivered
    __shared__ __align__(8) unsigned long long mbarR[2]; // peer-half p (+rv) delivered

    const int tid  = threadIdx.x;
    const int w    = tid >> 5;
    const int lane = tid & 31;
    const int jb   = w & 3;
    const int ic   = w >> 2;             // 0..3
    const int jl   = jb * 32 + lane;     // local j, 0..127 (== tid for tid<128)

    uint32_t rank; asm("mov.u32 %0, %%cluster_ctarank;" : "=r"(rank));
    const uint32_t peer = rank ^ 1u;
    const int b  = blockIdx.x >> 1;
    const int jg = (int)rank * 128 + jl;
    // Rank-aware chunk map: chunks 0,1 cover the LOCAL 128 i-columns.
    const int i0 = ((ic + 2 * (int)rank) & 3) * 64;
    const bool needs_peer = (ic >= 2);

    // ---------------- setup ----------------
    if (tid == 0) {
        mbar_init(smem_u32(&mbarL[0]), 1);
        mbar_init(smem_u32(&mbarL[1]), 1);
        mbar_init(smem_u32(&mbarR[0]), 1);
        mbar_init(smem_u32(&mbarR[1]), 1);
        rv_s[0] = 1.0f; rv_s[1] = 1.0f;
    }
    // len = sum(mask row b)  (mask is a 1...10...0 prefix)
    {
        float ms = 0.0f;
        for (int i = tid; i < TSZ; i += 512) ms += mask[(size_t)b * TSZ + i];
        #pragma unroll
        for (int o = 16; o; o >>= 1) ms += __shfl_xor_sync(0xffffffffu, ms, o);
        if (lane == 0) lred_s[w] = ms;
    }
    if (tid < 128) {
        const float* row = trans + (size_t)((int)rank * 128 + tid) * KSZ;
        float mx = row[0];
        #pragma unroll 8
        for (int i = 1; i < KSZ; i++) mx = fmaxf(mx, row[i]);
        Mrow_s[tid] = mx;
    }
    for (int i = tid; i < KSZ; i += 512) p_s[0][i] = (i == SOSI) ? 1.0f : 0.0f;
    __syncthreads();
    if (tid == 0) {
        float s = 0.0f;
        #pragma unroll
        for (int k = 0; k < 16; k++) s += lred_s[k];
        len_s = (int)(s + 0.5f);
    }

    // Register-resident E chunk: 64 columns [i0, i0+64) of row jg, as 32 f32x2.
    unsigned long long E2[32];
    {
        const float Mj0 = Mrow_s[jl];
        const float* row = trans + (size_t)jg * KSZ + i0;
        #pragma unroll 8
        for (int k = 0; k < 32; k++) {
            float e0 = ex2f((row[2 * k]     - Mj0) * INV_LN2);
            float e1 = ex2f((row[2 * k + 1] - Mj0) * INV_LN2);
            E2[k] = pack2(e0, e1);
        }
    }

    // Tail-thread state + delivery addresses.
    float Mj = 0.0f, pv = 0.0f, c_run = 0.0f, vstar = 1.0f;
    float yx_n = 0.0f, y_r = 0.0f;
    uint32_t pa_p0 = 0, pa_p1 = 0, pa_bR0 = 0, pa_bR1 = 0;
    uint32_t la_p0 = 0, la_p1 = 0, la_bL0 = 0, la_bL1 = 0;
    uint32_t pa_rv0 = 0, pa_rv1 = 0;
    if (tid < 128) {
        Mj = Mrow_s[tid];
        // even lanes send the (tid, tid+1) pair
        const int je = jg & ~1;
        pa_p0  = mapa_u32(smem_u32(&p_s[0][je]), peer);
        pa_p1  = mapa_u32(smem_u32(&p_s[1][je]), peer);
        pa_bR0 = mapa_u32(smem_u32(&mbarR[0]), peer);
        pa_bR1 = mapa_u32(smem_u32(&mbarR[1]), peer);
        la_p0  = mapa_u32(smem_u32(&p_s[0][je]), rank);
        la_p1  = mapa_u32(smem_u32(&p_s[1][je]), rank);
        la_bL0 = mapa_u32(smem_u32(&mbarL[0]), rank);
        la_bL1 = mapa_u32(smem_u32(&mbarL[1]), rank);
        if (rank == 0 && tid == JSTAR) {
            pa_rv0 = mapa_u32(smem_u32(&rv_s[0]), peer);
            pa_rv1 = mapa_u32(smem_u32(&rv_s[1]), peer);
        }
        // y pipeline: yexp = exp2((y + Mj)*INV_LN2), one step ahead.
        const float* ybase = y + (size_t)b * TSZ * KSZ + jg;
        yx_n = ex2f((__ldg(ybase) + Mj) * INV_LN2);
        y_r  = __ldg(ybase + KSZ);
    }
    const float* ybase = y + (size_t)b * TSZ * KSZ + jg;

    __syncthreads();
    cluster_barrier();     // mbar init + p0 visible cluster-wide
    const int len = len_s;

    // ---------------- sequential scan ----------------
    for (int t = 0; t < len; t++) {
        const int pb = t & 1;

        if (tid == 0 && t > 0) {
            mbar_expect_tx(smem_u32(&mbarL[pb]), 512);
            mbar_expect_tx(smem_u32(&mbarR[pb]), (rank == 1) ? 516 : 512);
        }

        // Off-path: y pipeline for the tail (independent of the waits).
        float yx_c = yx_n;
        if (tid < 128) {
            yx_n = ex2f((y_r + Mj) * INV_LN2);
            if (t + 2 < TSZ) y_r = __ldg(ybase + (size_t)(t + 2) * KSZ);
        }

        if (t > 0) {
            const unsigned par = ((unsigned)(t >> 1) + (unsigned)(t & 1) + 1u) & 1u;
            if (needs_peer) mbar_wait_parity(smem_u32(&mbarR[pb]), par);
            else            mbar_wait_parity(smem_u32(&mbarL[pb]), par);
        }

        // 64-wide chunk dot-product: 32 packed FMAs.
        unsigned long long a0 = 0ull, a1 = 0ull, a2 = 0ull, a3 = 0ull;
        const ulonglong2* pp = reinterpret_cast<const ulonglong2*>(p_s[pb] + i0);
        #pragma unroll
        for (int q = 0; q < 8; q++) {
            ulonglong2 v1 = pp[2 * q];          // broadcast LDS.128
            ulonglong2 v2 = pp[2 * q + 1];
            fma2(a0, E2[4 * q],     v1.x);
            fma2(a1, E2[4 * q + 1], v1.y);
            fma2(a2, E2[4 * q + 2], v2.x);
            fma2(a3, E2[4 * q + 3], v2.y);
        }
        float x0, x1, x2, x3, x4, x5, x6, x7;
        unpack2(a0, x0, x1); unpack2(a1, x2, x3);
        unpack2(a2, x4, x5); unpack2(a3, x6, x7);
        partial_s[pb][ic][jl] = ((x0 + x2) + (x1 + x3)) + ((x4 + x6) + (x5 + x7));
        __syncthreads();

        if (tid < 128) {
            const float rv = rv_s[pb];
            const float v  = (partial_s[pb][0][tid] + partial_s[pb][1][tid]) +
                             (partial_s[pb][2][tid] + partial_s[pb][3][tid]);
            const float pn = yx_c * v * rv;           // P_{t+1}[jg]
            pv = pn;
            const float hi = __shfl_xor_sync(0xffffffffu, pn, 1);
            if ((lane & 1) == 0) {
                const unsigned long long pk = pack2(pn, hi);
                st_async_b64(pb ? pa_p0 : pa_p1, pk, pb ? pa_bR0 : pa_bR1); // peer (slow)
                st_async_b64(pb ? la_p0 : la_p1, pk, pb ? la_bL0 : la_bL1); // local (fast)
            }
            if (rank == 0 && tid == JSTAR) {          // off-path shift bookkeeping
                c_run += lg2f_(vstar) * LN2F;
                vstar  = v;
                const float rvn = rcpf_(v);
                rv_s[pb ^ 1] = rvn;                               // own copy (plain STS)
                st_async_b32(pb ? pa_rv0 : pa_rv1, rvn,           // peer copy
                             pb ? pa_bR0 : pa_bR1);
            }
        }
    }

    // ---------------- final: out = C + ln(sum_j P) ----------------
    if (tid < 128) {
        sfin_s[tid] = pv;
        if (rank == 0 && tid == JSTAR) c_s = c_run;
    }
    __syncthreads();
    float sum = 0.0f;
    if (tid < 32) {
        sum = (sfin_s[tid] + sfin_s[tid + 32]) + (sfin_s[tid + 64] + sfin_s[tid + 96]);
        #pragma unroll
        for (int o = 16; o; o >>= 1) sum += __shfl_xor_sync(0xffffffffu, sum, o);
        if (tid == 0 && rank == 1)
            st_cl(mapa_u32(smem_u32(&fin_s), 0u), sum);
    }
    cluster_barrier();                                // fin_s delivered
    if (rank == 0 && tid == 0)
        out[b] = c_s + lg2f_(sum + fin_s) * LN2F;
    cluster_barrier();                                // no exit with peer stores in flight
}

extern "C" void kernel_launch(void* const* d_in, const int* in_sizes, int n_in,
                              void* d_out, int out_size)
{
    const float* y     = (const float*)d_in[0];   // (B, T, K) f32
    const float* mask  = (const float*)d_in[1];   // (B, T)    f32
    const float* trans = (const float*)d_in[2];   // (K, K)    f32
    float* out = (float*)d_out;                   // (B,)      f32

    const int B = in_sizes[1] / TSZ;              // 64
    crf_fwd_kernel<<<2 * B, 512>>>(y, mask, trans, out);
}

// round 15
// speedup vs baseline: 1.1588x; 1.1588x over previous
#include <cuda_runtime.h>
#include <cstdint>

// CRF forward (linear-chain log-partition), B=64, T=2048, K=256.
// 1 cluster (2 CTAs) per batch row, 512 threads/CTA. Row-split (R5 skeleton):
// CTA r owns next-states j in [r*128, r*128+128); E[j,i]=exp(trans[j,i]-Mj)
// register-resident (64 fp32/thread, 4 threads per j over 64-wide i-chunks).
// Exp-domain scores P = exp(s - C): tail is P' = yexp * v * rv (no
// transcendentals on the serial path; yexp pipelined, rv = 1/v* lagged by one
// step, maintained off-path by thread JSTAR on rank 0). Tail publishes its
// half of P via plain STS locally (ordered by bar.sync 1,256 over warps 0-7)
// and 128 x st.async b32 to the peer (tx-mbarrier, double-buffered).
// Rank-aware chunk map: tail warps always consume LOCAL i-columns, so no tail
// ever waits on the mbarrier. Mask is a prefix: loop runs t < len only.

#define KSZ 256
#define TSZ 2048
#define SOSI 2
#define JSTAR 16

__device__ __forceinline__ float ex2f(float x) {
    float r; asm("ex2.approx.ftz.f32 %0, %1;" : "=f"(r) : "f"(x)); return r;
}
__device__ __forceinline__ float lg2f_(float x) {
    float r; asm("lg2.approx.ftz.f32 %0, %1;" : "=f"(r) : "f"(x)); return r;
}
__device__ __forceinline__ float rcpf_(float x) {
    float r; asm("rcp.approx.ftz.f32 %0, %1;" : "=f"(r) : "f"(x)); return r;
}
__device__ __forceinline__ void unpack2(unsigned long long v, float& lo, float& hi) {
    asm("mov.b64 {%0, %1}, %2;" : "=f"(lo), "=f"(hi) : "l"(v));
}
__device__ __forceinline__ unsigned long long pack2(float lo, float hi) {
    unsigned long long r; asm("mov.b64 %0, {%1, %2};" : "=l"(r) : "f"(lo), "f"(hi)); return r;
}
__device__ __forceinline__ void fma2(unsigned long long& d, unsigned long long a, unsigned long long b) {
    asm("fma.rn.f32x2 %0, %1, %2, %0;" : "+l"(d) : "l"(a), "l"(b));
}
__device__ __forceinline__ uint32_t smem_u32(const void* p) {
    uint32_t a;
    asm("{ .reg .u64 t; cvta.to.shared.u64 t, %1; cvt.u32.u64 %0, t; }" : "=r"(a) : "l"(p));
    return a;
}
__device__ __forceinline__ uint32_t mapa_u32(uint32_t a, uint32_t rk) {
    uint32_t r; asm("mapa.shared::cluster.u32 %0, %1, %2;" : "=r"(r) : "r"(a), "r"(rk)); return r;
}
__device__ __forceinline__ void st_cl(uint32_t a, float v) {
    asm volatile("st.shared::cluster.f32 [%0], %1;" :: "r"(a), "f"(v));
}
__device__ __forceinline__ void st_async_b32(uint32_t dst_addr, float v, uint32_t dst_bar) {
    asm volatile("st.async.shared::cluster.mbarrier::complete_tx::bytes.b32 [%0], %1, [%2];"
                 :: "r"(dst_addr), "r"(__float_as_uint(v)), "r"(dst_bar) : "memory");
}
__device__ __forceinline__ void mbar_init(uint32_t bar, uint32_t cnt) {
    asm volatile("mbarrier.init.shared.b64 [%0], %1;" :: "r"(bar), "r"(cnt) : "memory");
}
__device__ __forceinline__ void mbar_expect_tx(uint32_t bar, uint32_t bytes) {
    asm volatile("mbarrier.arrive.expect_tx.shared.b64 _, [%0], %1;" :: "r"(bar), "r"(bytes) : "memory");
}
__device__ __forceinline__ void mbar_wait_parity(uint32_t bar, uint32_t par) {
    asm volatile(
        "{\n\t.reg .pred P;\n\t"
        "WL_%=:\n\t"
        "mbarrier.try_wait.parity.acquire.cta.shared::cta.b64 P, [%0], %1, 0x989680;\n\t"
        "@P bra.uni WD_%=;\n\t"
        "bra.uni WL_%=;\n\t"
        "WD_%=:\n\t}"
        :: "r"(bar), "r"(par) : "memory");
}
__device__ __forceinline__ void cluster_barrier() {
    asm volatile("barrier.cluster.arrive.aligned;" ::: "memory");
    asm volatile("barrier.cluster.wait.aligned;"   ::: "memory");
}

__global__ void __cluster_dims__(2, 1, 1) __launch_bounds__(512, 1)
crf_fwd_kernel(const float* __restrict__ y,
               const float* __restrict__ mask,
               const float* __restrict__ trans,
               float* __restrict__ out)
{
    constexpr float INV_LN2 = 1.4426950408889634f;
    constexpr float LN2F    = 0.6931471805599453f;

    __shared__ __align__(16) float p_s[2][KSZ];     // full P vector, double-buffered
    __shared__ float partial_s[4][128];             // per-chunk partials
    __shared__ float Mrow_s[128];                   // rowmax of local trans rows
    __shared__ float rv_s[2];                       // lagged 1/v*
    __shared__ float c_s;                           // final shift (rank 0)
    __shared__ float sfin_s[128];                   // final P, own half
    __shared__ float fin_s;                         // peer's half-sum
    __shared__ float lred_s[16];
    __shared__ int   len_s;
    __shared__ __align__(8) unsigned long long mbar[2]; // peer P (+rv) delivered (tx)

    const int tid  = threadIdx.x;
    const int w    = tid >> 5;
    const int lane = tid & 31;
    const int jb   = w & 3;
    const int ic   = w >> 2;             // 0..3
    const int jl   = jb * 32 + lane;     // local j, 0..127 (== tid for tid<128)

    uint32_t rank; asm("mov.u32 %0, %%cluster_ctarank;" : "=r"(rank));
    const uint32_t peer = rank ^ 1u;
    const int b  = blockIdx.x >> 1;
    const int jg = (int)rank * 128 + jl;
    // Rank-aware chunk map: chunks ic=0,1 always cover this CTA's LOCAL 128
    // i-columns (tail warps never wait the mbar); ic=2,3 cover the peer's.
    const int  i0         = ((ic + 2 * (int)rank) & 3) * 64;
    const bool needs_peer = (ic >= 2);

    // ---------------- setup ----------------
    if (tid == 0) {
        mbar_init(smem_u32(&mbar[0]), 1);
        mbar_init(smem_u32(&mbar[1]), 1);
        rv_s[0] = 1.0f; rv_s[1] = 1.0f;
    }
    // len = sum(mask row b): mask is a 1...10...0 prefix.
    {
        float ms = 0.0f;
        for (int i = tid; i < TSZ; i += 512) ms += mask[(size_t)b * TSZ + i];
        #pragma unroll
        for (int o = 16; o; o >>= 1) ms += __shfl_xor_sync(0xffffffffu, ms, o);
        if (lane == 0) lred_s[w] = ms;
    }
    if (tid < 128) {
        const float* row = trans + (size_t)((int)rank * 128 + tid) * KSZ;
        float mx = row[0];
        #pragma unroll 8
        for (int i = 1; i < KSZ; i++) mx = fmaxf(mx, row[i]);
        Mrow_s[tid] = mx;
    }
    for (int i = tid; i < KSZ; i += 512) p_s[0][i] = (i == SOSI) ? 1.0f : 0.0f;
    __syncthreads();
    if (tid == 0) {
        float s = 0.0f;
        #pragma unroll
        for (int k = 0; k < 16; k++) s += lred_s[k];
        len_s = (int)(s + 0.5f);
    }

    // Register-resident E chunk: 64 columns [i0, i0+64) of row jg, as 32 f32x2.
    unsigned long long E2[32];
    {
        const float Mj0 = Mrow_s[jl];
        const float* row = trans + (size_t)jg * KSZ + i0;
        #pragma unroll 8
        for (int k = 0; k < 32; k++) {
            float e0 = ex2f((row[2 * k]     - Mj0) * INV_LN2);
            float e1 = ex2f((row[2 * k + 1] - Mj0) * INV_LN2);
            E2[k] = pack2(e0, e1);
        }
    }

    // Tail-thread state + peer delivery addresses.
    float Mj = 0.0f, pv = 0.0f, c_run = 0.0f, vstar = 1.0f;
    float yx_n = 0.0f, y_r = 0.0f;
    uint32_t pa_p0 = 0, pa_p1 = 0, pa_b0 = 0, pa_b1 = 0;
    uint32_t pa_rv0 = 0, pa_rv1 = 0;
    const float* ybase = y + (size_t)b * TSZ * KSZ + jg;
    if (tid < 128) {
        Mj    = Mrow_s[tid];
        pa_p0 = mapa_u32(smem_u32(&p_s[0][jg]), peer);
        pa_p1 = mapa_u32(smem_u32(&p_s[1][jg]), peer);
        pa_b0 = mapa_u32(smem_u32(&mbar[0]), peer);
        pa_b1 = mapa_u32(smem_u32(&mbar[1]), peer);
        if (rank == 0 && tid == JSTAR) {
            pa_rv0 = mapa_u32(smem_u32(&rv_s[0]), peer);
            pa_rv1 = mapa_u32(smem_u32(&rv_s[1]), peer);
        }
        // y pipeline: yexp = exp2((y + Mj) * INV_LN2), one step ahead.
        yx_n = ex2f((__ldg(ybase) + Mj) * INV_LN2);
        y_r  = __ldg(ybase + KSZ);
    }

    __syncthreads();
    cluster_barrier();     // mbar init + p0 + rv visible cluster-wide
    const int len = len_s;

    // ---------------- sequential scan ----------------
    for (int t = 0; t < len; t++) {
        const int pb = t & 1, nb = pb ^ 1;

        if (tid == 0 && t > 0)
            mbar_expect_tx(smem_u32(&mbar[pb]), (rank == 1) ? 516 : 512);

        // Off-path: y pipeline for the tail (independent of all waits).
        const float yx_c = yx_n;
        if (tid < 128) {
            yx_n = ex2f((y_r + Mj) * INV_LN2);
            if (t + 2 < TSZ) y_r = __ldg(ybase + (size_t)(t + 2) * KSZ);
        }

        if (t > 0 && needs_peer) {
            const unsigned par = ((unsigned)(t >> 1) + (unsigned)(t & 1) + 1u) & 1u;
            mbar_wait_parity(smem_u32(&mbar[pb]), par);
        }

        // 64-wide chunk dot-product: 32 packed FMAs.
        unsigned long long a0 = 0ull, a1 = 0ull, a2 = 0ull, a3 = 0ull;
        const ulonglong2* pp = reinterpret_cast<const ulonglong2*>(p_s[pb] + i0);
        #pragma unroll
        for (int q = 0; q < 8; q++) {
            ulonglong2 v1 = pp[2 * q];          // broadcast LDS.128
            ulonglong2 v2 = pp[2 * q + 1];
            fma2(a0, E2[4 * q],     v1.x);
            fma2(a1, E2[4 * q + 1], v1.y);
            fma2(a2, E2[4 * q + 2], v2.x);
            fma2(a3, E2[4 * q + 3], v2.y);
        }
        float x0, x1, x2, x3, x4, x5, x6, x7;
        unpack2(a0, x0, x1); unpack2(a1, x2, x3);
        unpack2(a2, x4, x5); unpack2(a3, x6, x7);
        partial_s[ic][jl] = ((x0 + x2) + (x1 + x3)) + ((x4 + x6) + (x5 + x7));
        __syncthreads();

        // Tail: exp-domain recurrence, no transcendentals on the serial path.
        if (tid < 128) {
            const float rv = rv_s[pb];
            const float v  = (partial_s[0][tid] + partial_s[1][tid]) +
                             (partial_s[2][tid] + partial_s[3][tid]);
            const float pn = yx_c * v * rv;           // P_{t+1}[jg]
            pv = pn;
            p_s[nb][jg] = pn;                                     // local publish (STS)
            st_async_b32(pb ? pa_p0 : pa_p1, pn,                  // peer publish
                         pb ? pa_b0 : pa_b1);
            if (rank == 0 && tid == JSTAR) {          // off-path shift bookkeeping
                c_run += lg2f_(vstar) * LN2F;         // C += ln v*_{t-1}
                vstar  = v;
                const float rvn = rcpf_(v);
                rv_s[nb] = rvn;                                   // own copy (STS)
                st_async_b32(pb ? pa_rv0 : pa_rv1, rvn,           // peer copy
                             pb ? pa_b0 : pa_b1);
            }
        }
        // Order tail STS (p, rv) before warps 0-7 read them next step.
        // Warps 8-15 are ordered by the mbar <-> tail-send dependency chain.
        if (w < 8) asm volatile("bar.sync 1, 256;" ::: "memory");
    }

    // ---------------- final: out = C + ln(sum_j P) ----------------
    if (tid < 128) {
        sfin_s[tid] = pv;
        if (rank == 0 && tid == JSTAR) c_s = c_run + lg2f_(vstar) * 0.0f; // c_run = C_len
    }
    __syncthreads();
    float sum = 0.0f;
    if (tid < 32) {
        sum = (sfin_s[tid] + sfin_s[tid + 32]) + (sfin_s[tid + 64] + sfin_s[tid + 96]);
        #pragma unroll
        for (int o = 16; o; o >>= 1) sum += __shfl_xor_sync(0xffffffffu, sum, o);
        if (tid == 0 && rank == 1)
            st_cl(mapa_u32(smem_u32(&fin_s), 0u), sum);
    }
    cluster_barrier();                                // fin_s delivered
    if (rank == 0 && tid == 0)
        out[b] = c_s + lg2f_(sum + fin_s) * LN2F;
    cluster_barrier();                                // no exit with peer stores in flight
}

extern "C" void kernel_launch(void* const* d_in, const int* in_sizes, int n_in,
                              void* d_out, int out_size)
{
    const float* y     = (const float*)d_in[0];   // (B, T, K) f32
    const float* mask  = (const float*)d_in[1];   // (B, T)    f32
    const float* trans = (const float*)d_in[2];   // (K, K)    f32
    float* out = (float*)d_out;                   // (B,)      f32

    const int B = in_sizes[1] / TSZ;              // 64
    crf_fwd_kernel<<<2 * B, 512>>>(y, mask, trans, out);
}

// round 17
// speedup vs baseline: 1.2189x; 1.0519x over previous
#include <cuda_runtime.h>
#include <cstdint>

// CRF forward (linear-chain log-partition), B=64, T=2048, K=256.
// 1 cluster (2 CTAs) per batch row, 512 threads/CTA, FULLY LOCKSTEP loop
// (two __syncthreads per step — no free-running warps, no partial barriers).
// Row-split: CTA r owns next-states j in [r*128, r*128+128);
// E[j,i]=exp(trans[j,i]-Mj) register-resident (64 fp32/thread, 4 threads/j
// over 64-wide i-chunks, rank-aware so tail warps consume LOCAL columns).
// Exp-domain scores P = exp(s - C): tail (64 threads x 2 rows) computes
// P' = yexp * v * rv with no transcendentals on the serial path (yexp
// pipelined; rv = 1/v* lagged one step, ref thread does one MUFU.RCP).
// v* history goes to smem; C = sum(ln v*) computed once after the loop.
// Tail publishes P via STS.64 locally and 64 x st.async.b64 to the peer.
// Mask is a prefix: loop runs t < len = sum(mask).

#define KSZ 256
#define TSZ 2048
#define SOSI 2
#define RT   8      // reference tail thread (rank 0): uses v of row 2*RT = 16

__device__ __forceinline__ float ex2f(float x) {
    float r; asm("ex2.approx.ftz.f32 %0, %1;" : "=f"(r) : "f"(x)); return r;
}
__device__ __forceinline__ float lg2f_(float x) {
    float r; asm("lg2.approx.ftz.f32 %0, %1;" : "=f"(r) : "f"(x)); return r;
}
__device__ __forceinline__ float rcpf_(float x) {
    float r; asm("rcp.approx.ftz.f32 %0, %1;" : "=f"(r) : "f"(x)); return r;
}
__device__ __forceinline__ void unpack2(unsigned long long v, float& lo, float& hi) {
    asm("mov.b64 {%0, %1}, %2;" : "=f"(lo), "=f"(hi) : "l"(v));
}
__device__ __forceinline__ unsigned long long pack2(float lo, float hi) {
    unsigned long long r; asm("mov.b64 %0, {%1, %2};" : "=l"(r) : "f"(lo), "f"(hi)); return r;
}
__device__ __forceinline__ void fma2(unsigned long long& d, unsigned long long a, unsigned long long b) {
    asm("fma.rn.f32x2 %0, %1, %2, %0;" : "+l"(d) : "l"(a), "l"(b));
}
__device__ __forceinline__ uint32_t smem_u32(const void* p) {
    uint32_t a;
    asm("{ .reg .u64 t; cvta.to.shared.u64 t, %1; cvt.u32.u64 %0, t; }" : "=r"(a) : "l"(p));
    return a;
}
__device__ __forceinline__ uint32_t mapa_u32(uint32_t a, uint32_t rk) {
    uint32_t r; asm("mapa.shared::cluster.u32 %0, %1, %2;" : "=r"(r) : "r"(a), "r"(rk)); return r;
}
__device__ __forceinline__ void st_cl(uint32_t a, float v) {
    asm volatile("st.shared::cluster.f32 [%0], %1;" :: "r"(a), "f"(v));
}
__device__ __forceinline__ void st_async_b64(uint32_t dst_addr, unsigned long long v, uint32_t dst_bar) {
    asm volatile("st.async.shared::cluster.mbarrier::complete_tx::bytes.b64 [%0], %1, [%2];"
                 :: "r"(dst_addr), "l"(v), "r"(dst_bar) : "memory");
}
__device__ __forceinline__ void st_async_b32(uint32_t dst_addr, float v, uint32_t dst_bar) {
    asm volatile("st.async.shared::cluster.mbarrier::complete_tx::bytes.b32 [%0], %1, [%2];"
                 :: "r"(dst_addr), "r"(__float_as_uint(v)), "r"(dst_bar) : "memory");
}
__device__ __forceinline__ void mbar_init(uint32_t bar, uint32_t cnt) {
    asm volatile("mbarrier.init.shared.b64 [%0], %1;" :: "r"(bar), "r"(cnt) : "memory");
}
__device__ __forceinline__ void mbar_expect_tx(uint32_t bar, uint32_t bytes) {
    asm volatile("mbarrier.arrive.expect_tx.shared.b64 _, [%0], %1;" :: "r"(bar), "r"(bytes) : "memory");
}
__device__ __forceinline__ void mbar_wait_parity(uint32_t bar, uint32_t par) {
    asm volatile(
        "{\n\t.reg .pred P;\n\t"
        "WL_%=:\n\t"
        "mbarrier.try_wait.parity.acquire.cta.shared::cta.b64 P, [%0], %1, 0x989680;\n\t"
        "@P bra.uni WD_%=;\n\t"
        "bra.uni WL_%=;\n\t"
        "WD_%=:\n\t}"
        :: "r"(bar), "r"(par) : "memory");
}
__device__ __forceinline__ void cluster_barrier() {
    asm volatile("barrier.cluster.arrive.aligned;" ::: "memory");
    asm volatile("barrier.cluster.wait.aligned;"   ::: "memory");
}

__global__ void __cluster_dims__(2, 1, 1) __launch_bounds__(512, 1)
crf_fwd_kernel(const float* __restrict__ y,
               const float* __restrict__ mask,
               const float* __restrict__ trans,
               float* __restrict__ out)
{
    constexpr float INV_LN2 = 1.4426950408889634f;
    constexpr float LN2F    = 0.6931471805599453f;

    __shared__ __align__(16) float p_s[2][KSZ];     // full P vector, double-buffered
    __shared__ __align__(8)  float partial_s[4][128]; // per-chunk partials
    __shared__ float Mrow_s[128];                   // rowmax of local trans rows
    __shared__ float rv_s[2];                       // lagged 1/v*
    __shared__ float vhist_s[TSZ];                  // v* history (rank 0), 8 KB
    __shared__ __align__(8) float sfin_s[128];      // final P, own half
    __shared__ float fin_s;                         // peer's half-sum
    __shared__ float lred_s[16];
    __shared__ int   len_s;
    __shared__ __align__(8) unsigned long long mbar[2]; // peer P (+rv) delivered (tx)

    const int tid  = threadIdx.x;
    const int w    = tid >> 5;
    const int lane = tid & 31;
    const int jb   = w & 3;
    const int ic   = w >> 2;             // 0..3
    const int jl   = jb * 32 + lane;     // local j for the E chunk, 0..127

    uint32_t rank; asm("mov.u32 %0, %%cluster_ctarank;" : "=r"(rank));
    const uint32_t peer = rank ^ 1u;
    const int b  = blockIdx.x >> 1;
    const int jg = (int)rank * 128 + jl;
    // Rank-aware chunk map: ic=0,1 cover this CTA's LOCAL 128 i-columns
    // (tail warps 0-1 have ic=0 and never wait the mbar); ic=2,3 the peer's.
    const int  i0         = ((ic + 2 * (int)rank) & 3) * 64;
    const bool needs_peer = (ic >= 2);

    // ---------------- setup ----------------
    if (tid == 0) {
        mbar_init(smem_u32(&mbar[0]), 1);
        mbar_init(smem_u32(&mbar[1]), 1);
        rv_s[0] = 1.0f; rv_s[1] = 1.0f;
    }
    // len = sum(mask row b): mask is a 1...10...0 prefix.
    {
        float ms = 0.0f;
        for (int i = tid; i < TSZ; i += 512) ms += mask[(size_t)b * TSZ + i];
        #pragma unroll
        for (int o = 16; o; o >>= 1) ms += __shfl_xor_sync(0xffffffffu, ms, o);
        if (lane == 0) lred_s[w] = ms;
    }
    if (tid < 128) {
        const float* row = trans + (size_t)((int)rank * 128 + tid) * KSZ;
        float mx = row[0];
        #pragma unroll 8
        for (int i = 1; i < KSZ; i++) mx = fmaxf(mx, row[i]);
        Mrow_s[tid] = mx;
    }
    for (int i = tid; i < KSZ; i += 512) p_s[0][i] = (i == SOSI) ? 1.0f : 0.0f;
    __syncthreads();
    if (tid == 0) {
        float s = 0.0f;
        #pragma unroll
        for (int k = 0; k < 16; k++) s += lred_s[k];
        len_s = (int)(s + 0.5f);
    }

    // Register-resident E chunk: 64 columns [i0, i0+64) of row jg, as 32 f32x2.
    unsigned long long E2[32];
    {
        const float Mj0 = Mrow_s[jl];
        const float* row = trans + (size_t)jg * KSZ + i0;
        #pragma unroll 8
        for (int k = 0; k < 32; k++) {
            float e0 = ex2f((row[2 * k]     - Mj0) * INV_LN2);
            float e1 = ex2f((row[2 * k + 1] - Mj0) * INV_LN2);
            E2[k] = pack2(e0, e1);
        }
    }

    // Tail threads: tid < 64, each owns row pair (2*tid, 2*tid+1) of this rank.
    float Mj0 = 0.0f, Mj1 = 0.0f, pv0 = 0.0f, pv1 = 0.0f;
    float yx0 = 0.0f, yx1 = 0.0f;
    float2 y_r = make_float2(0.0f, 0.0f);
    uint32_t pa_p0 = 0, pa_p1 = 0, pa_b0 = 0, pa_b1 = 0;
    uint32_t pa_rv0 = 0, pa_rv1 = 0;
    const int j2  = 2 * tid;                       // local row pair base (tail only)
    const int jg2 = (int)rank * 128 + j2;          // global row pair base
    const float2* yb2 = reinterpret_cast<const float2*>(y + (size_t)b * TSZ * KSZ) + (jg2 >> 1);
    if (tid < 64) {
        Mj0   = Mrow_s[j2];
        Mj1   = Mrow_s[j2 + 1];
        pa_p0 = mapa_u32(smem_u32(&p_s[0][jg2]), peer);
        pa_p1 = mapa_u32(smem_u32(&p_s[1][jg2]), peer);
        pa_b0 = mapa_u32(smem_u32(&mbar[0]), peer);
        pa_b1 = mapa_u32(smem_u32(&mbar[1]), peer);
        if (rank == 0 && tid == RT) {
            pa_rv0 = mapa_u32(smem_u32(&rv_s[0]), peer);
            pa_rv1 = mapa_u32(smem_u32(&rv_s[1]), peer);
        }
        // y pipeline, one step ahead: yexp = exp2((y + Mj) * INV_LN2).
        float2 y0 = __ldg(yb2);
        yx0 = ex2f((y0.x + Mj0) * INV_LN2);
        yx1 = ex2f((y0.y + Mj1) * INV_LN2);
        y_r = __ldg(yb2 + (KSZ >> 1));
    }

    __syncthreads();
    cluster_barrier();     // mbar init + p0 + rv visible cluster-wide
    const int len = len_s;

    // ---------------- sequential scan (fully lockstep) ----------------
    for (int t = 0; t < len; t++) {
        const int pb = t & 1, nb = pb ^ 1;

        if (tid == 0 && t > 0)
            mbar_expect_tx(smem_u32(&mbar[pb]), (rank == 1) ? 516 : 512);

        // Off-path: y pipeline for the tail (independent of all waits).
        const float yxc0 = yx0, yxc1 = yx1;
        if (tid < 64) {
            yx0 = ex2f((y_r.x + Mj0) * INV_LN2);
            yx1 = ex2f((y_r.y + Mj1) * INV_LN2);
            if (t + 2 < TSZ) y_r = __ldg(yb2 + (size_t)(t + 2) * (KSZ >> 1));
        }

        if (t > 0 && needs_peer) {
            const unsigned par = ((unsigned)(t >> 1) + (unsigned)(t & 1) + 1u) & 1u;
            mbar_wait_parity(smem_u32(&mbar[pb]), par);
        }

        // 64-wide chunk dot-product: 32 packed FMAs.
        unsigned long long a0 = 0ull, a1 = 0ull, a2 = 0ull, a3 = 0ull;
        const ulonglong2* pp = reinterpret_cast<const ulonglong2*>(p_s[pb] + i0);
        #pragma unroll
        for (int q = 0; q < 8; q++) {
            ulonglong2 v1 = pp[2 * q];          // broadcast LDS.128
            ulonglong2 v2 = pp[2 * q + 1];
            fma2(a0, E2[4 * q],     v1.x);
            fma2(a1, E2[4 * q + 1], v1.y);
            fma2(a2, E2[4 * q + 2], v2.x);
            fma2(a3, E2[4 * q + 3], v2.y);
        }
        float x0, x1, x2, x3, x4, x5, x6, x7;
        unpack2(a0, x0, x1); unpack2(a1, x2, x3);
        unpack2(a2, x4, x5); unpack2(a3, x6, x7);
        partial_s[ic][jl] = ((x0 + x2) + (x1 + x3)) + ((x4 + x6) + (x5 + x7));
        __syncthreads();

        // Tail: exp-domain recurrence over a row pair; no transcendentals.
        if (tid < 64) {
            const float rv = rv_s[pb];
            const float2 q0 = *reinterpret_cast<const float2*>(&partial_s[0][j2]);
            const float2 q1 = *reinterpret_cast<const float2*>(&partial_s[1][j2]);
            const float2 q2 = *reinterpret_cast<const float2*>(&partial_s[2][j2]);
            const float2 q3 = *reinterpret_cast<const float2*>(&partial_s[3][j2]);
            const float v0 = (q0.x + q1.x) + (q2.x + q3.x);
            const float v1 = (q0.y + q1.y) + (q2.y + q3.y);
            const float pn0 = yxc0 * v0 * rv;         // P_{t+1}[jg2]
            const float pn1 = yxc1 * v1 * rv;         // P_{t+1}[jg2+1]
            pv0 = pn0; pv1 = pn1;
            *reinterpret_cast<float2*>(&p_s[nb][jg2]) = make_float2(pn0, pn1);  // local
            st_async_b64(pb ? pa_p0 : pa_p1, pack2(pn0, pn1),                   // peer
                         pb ? pa_b0 : pa_b1);
            if (rank == 0 && tid == RT) {             // off-path shift bookkeeping
                vhist_s[t] = v0;                      // v* history (row 16)
                const float rvn = rcpf_(v0);
                rv_s[nb] = rvn;                                   // own copy (STS)
                st_async_b32(pb ? pa_rv0 : pa_rv1, rvn,           // peer copy
                             pb ? pa_b0 : pa_b1);
            }
        }
        __syncthreads();
    }

    // ---------------- final: out = C + ln(sum_j P),  C = sum ln v* ----------------
    if (tid < 64)
        *reinterpret_cast<float2*>(&sfin_s[j2]) = make_float2(pv0, pv1);
    __syncthreads();

    // Own half-sum of P.
    float sum = 0.0f;
    if (tid < 32) {
        sum = (sfin_s[tid] + sfin_s[tid + 32]) + (sfin_s[tid + 64] + sfin_s[tid + 96]);
        #pragma unroll
        for (int o = 16; o; o >>= 1) sum += __shfl_xor_sync(0xffffffffu, sum, o);
        if (tid == 0 && rank == 1)
            st_cl(mapa_u32(smem_u32(&fin_s), 0u), sum);
    }

    // C on rank 0: parallel sum of lg2(v*) over steps 0..len-2.
    float cpart = 0.0f;
    if (rank == 0) {
        for (int u = tid; u < len - 1; u += 512) cpart += lg2f_(vhist_s[u]);
        #pragma unroll
        for (int o = 16; o; o >>= 1) cpart += __shfl_xor_sync(0xffffffffu, cpart, o);
        if (lane == 0) lred_s[w] = cpart;
    }
    cluster_barrier();                                // fin_s delivered; lred ready
    if (rank == 0 && tid == 0) {
        float c = 0.0f;
        #pragma unroll
        for (int k = 0; k < 16; k++) c += lred_s[k];
        out[b] = c * LN2F + lg2f_(sum + fin_s) * LN2F;
    }
    cluster_barrier();                                // no exit with peer stores in flight
}

extern "C" void kernel_launch(void* const* d_in, const int* in_sizes, int n_in,
                              void* d_out, int out_size)
{
    const float* y     = (const float*)d_in[0];   // (B, T, K) f32
    const float* mask  = (const float*)d_in[1];   // (B, T)    f32
    const float* trans = (const float*)d_in[2];   // (K, K)    f32
    float* out = (float*)d_out;                   // (B,)      f32

    const int B = in_sizes[1] / TSZ;              // 64
    crf_fwd_kernel<<<2 * B, 512>>>(y, mask, trans, out);
}